// round 2
// baseline (speedup 1.0000x reference)
#include <cuda_runtime.h>
#include <cstdint>

#define Bb 32
#define Ss 256
#define Ll 64
#define Dd 100
#define Mm 20

// ---------------- scratch (no allocations allowed) ----------------
__device__ float g_enc[Bb * Ss * Dd];   // [B,S,D] encoded sentences
__device__ float g_sW [Bb * Ss * Dd];   // [B,S,D] enc @ W^T
__device__ float g_kg [Bb * Ss * Mm];   // [B,S,M] enc . keys[m]

// ---------------- f32x2 helpers ----------------
__device__ __forceinline__ void fma2(unsigned long long& acc,
                                     unsigned long long a,
                                     unsigned long long b) {
    asm("fma.rn.f32x2 %0, %1, %2, %0;" : "+l"(acc) : "l"(a), "l"(b));
}
__device__ __forceinline__ unsigned long long pack2(float lo, float hi) {
    unsigned long long r;
    asm("mov.b64 %0, {%1, %2};" : "=l"(r) : "f"(lo), "f"(hi));
    return r;
}
__device__ __forceinline__ float sum2(unsigned long long v) {
    float lo, hi;
    asm("mov.b64 {%0, %1}, %2;" : "=f"(lo), "=f"(hi) : "l"(v));
    return lo + hi;
}

// ================= K1: encode  enc[b,s,:] = sum_l batch[b,s,l,:]*mult[l,:] ==========
__global__ void k_encode(const float* __restrict__ batch,
                         const float* __restrict__ mult) {
    int row = blockIdx.x;          // b*S + s
    int e = threadIdx.x;
    if (e >= Dd) return;
    const float* bp = batch + (size_t)row * Ll * Dd + e;
    float acc = 0.f;
#pragma unroll 8
    for (int l = 0; l < Ll; ++l)
        acc += bp[(size_t)l * Dd] * __ldg(&mult[l * Dd + e]);
    g_enc[(size_t)row * Dd + e] = acc;
}

// ================= K2: project sW = enc @ W^T, kg = enc @ keys^T =================
#define R2 16
__global__ void k_project(const float* __restrict__ W,
                          const float* __restrict__ keys) {
    __shared__ float Wt[Dd * Dd];        // Wt[d*Dd + e] = W[e*Dd + d]  (40 KB)
    __shared__ float encs[R2][Dd];       // 6.4 KB
    int t = threadIdx.x;
    int row0 = blockIdx.x * R2;

    for (int idx = t; idx < Dd * Dd; idx += blockDim.x) {
        int e = idx / Dd, d = idx % Dd;
        Wt[d * Dd + e] = W[idx];
    }
    for (int idx = t; idx < R2 * Dd; idx += blockDim.x)
        ((float*)encs)[idx] = g_enc[(size_t)row0 * Dd + idx];
    __syncthreads();

    if (t < Dd) {
        for (int r = 0; r < R2; ++r) {
            float acc = 0.f;
#pragma unroll 4
            for (int d = 0; d < Dd; ++d)
                acc += encs[r][d] * Wt[d * Dd + t];   // consecutive t -> conflict-free
            g_sW[(size_t)(row0 + r) * Dd + t] = acc;
        }
    } else if (t < Dd + Mm) {
        int m = t - Dd;
        for (int r = 0; r < R2; ++r) {
            float acc = 0.f;
#pragma unroll 4
            for (int d = 0; d < Dd; ++d)
                acc += encs[r][d] * __ldg(&keys[m * Dd + d]);
            g_kg[(size_t)(row0 + r) * Mm + m] = acc;
        }
    }
}

// ================= K3: scan over S, one block per (b, m-pair) =================
__global__ void __launch_bounds__(128, 3)
k_scan(const float* __restrict__ keys, const float* __restrict__ U,
       const float* __restrict__ V, const float* __restrict__ prelu_a,
       float* __restrict__ out) {
    __shared__ __align__(16) float h0[128];   // 128: threads 100..127 zero-init in-bounds
    __shared__ __align__(16) float h1[128];
    __shared__ float2 redA[4];
    __shared__ float2 redB[4];

    int b  = blockIdx.y;
    int m0 = blockIdx.x * 2, m1 = m0 + 1;
    int e = threadIdx.x;
    int lane = e & 31, wid = e >> 5;
    float aprelu = __ldg(prelu_a);

    // U row of this output dim, packed into 50 b64 f32x2 registers
    unsigned long long U2[50];
    if (e < Dd) {
        const float2* up = (const float2*)(U + e * Dd);   // 400B stride: 8B aligned
#pragma unroll
        for (int i = 0; i < 50; ++i) {
            float2 u = __ldg(up + i);
            U2[i] = pack2(u.x, u.y);
        }
    } else {
#pragma unroll
        for (int i = 0; i < 50; ++i) U2[i] = 0ull;
    }

    // keysV[m,e] (step-invariant), and initial memory = keys
    float kv0 = 0.f, kv1 = 0.f, hold0 = 0.f, hold1 = 0.f;
    if (e < Dd) {
#pragma unroll 4
        for (int d = 0; d < Dd; ++d) {
            float ve = __ldg(&V[e * Dd + d]);
            kv0 += __ldg(&keys[m0 * Dd + d]) * ve;
            kv1 += __ldg(&keys[m1 * Dd + d]) * ve;
        }
        hold0 = __ldg(&keys[m0 * Dd + e]);
        hold1 = __ldg(&keys[m1 * Dd + e]);
        h0[e] = hold0;
        h1[e] = hold1;
    } else {
        h0[e] = 0.f;   // e in [100,128): in-bounds, race-free padding init
        h1[e] = 0.f;
    }

    const float* encp = g_enc + (size_t)b * Ss * Dd;
    const float* swp  = g_sW  + (size_t)b * Ss * Dd;
    const float* kgp  = g_kg  + (size_t)b * Ss * Mm;

    float encv = (e < Dd) ? encp[e] : 0.f;
    float swv  = (e < Dd) ? swp[e]  : 0.f;
    float kg0v = __ldg(&kgp[m0]);
    float kg1v = __ldg(&kgp[m1]);
    __syncthreads();

    const ulonglong2* h0q = (const ulonglong2*)h0;   // reads elements 0..99 only
    const ulonglong2* h1q = (const ulonglong2*)h1;

    for (int s = 0; s < Ss; ++s) {
        // ---- matvec: cand_pre[e] = sum_d h[d]*U[e,d]  (f32x2, 2 chains/slot) ----
        unsigned long long a0 = 0ull, a0b = 0ull, a1 = 0ull, a1b = 0ull;
#pragma unroll
        for (int i = 0; i < 25; ++i) {
            ulonglong2 x = h0q[i];
            ulonglong2 y = h1q[i];
            fma2(a0,  x.x, U2[2 * i]);
            fma2(a0b, x.y, U2[2 * i + 1]);
            fma2(a1,  y.x, U2[2 * i]);
            fma2(a1b, y.y, U2[2 * i + 1]);
        }

        // ---- memory gate dot: h . enc ----
        float p0 = hold0 * encv;
        float p1 = hold1 * encv;
#pragma unroll
        for (int o = 16; o > 0; o >>= 1) {
            p0 += __shfl_down_sync(0xffffffffu, p0, o);
            p1 += __shfl_down_sync(0xffffffffu, p1, o);
        }
        if (lane == 0) redA[wid] = make_float2(p0, p1);
        __syncthreads();   // redA ready; also: all matvec reads of h done

        float mg0 = redA[0].x + redA[1].x + redA[2].x + redA[3].x;
        float mg1 = redA[0].y + redA[1].y + redA[2].y + redA[3].y;
        float g0 = 1.f / (1.f + expf(-(mg0 + kg0v)));
        float g1 = 1.f / (1.f + expf(-(mg1 + kg1v)));

        float c0 = kv0 + swv + sum2(a0) + sum2(a0b);
        float c1 = kv1 + swv + sum2(a1) + sum2(a1b);
        c0 = (c0 >= 0.f) ? c0 : aprelu * c0;
        c1 = (c1 >= 0.f) ? c1 : aprelu * c1;

        float hn0 = hold0 + c0 * g0;
        float hn1 = hold1 + c1 * g1;
        if (e >= Dd) { hn0 = 0.f; hn1 = 0.f; }

        // ---- prefetch next step's inputs (hide gmem latency under norm) ----
        if (s + 1 < Ss) {
            encv = (e < Dd) ? encp[(size_t)(s + 1) * Dd + e] : 0.f;
            swv  = (e < Dd) ? swp[(size_t)(s + 1) * Dd + e]  : 0.f;
            kg0v = __ldg(&kgp[(size_t)(s + 1) * Mm + m0]);
            kg1v = __ldg(&kgp[(size_t)(s + 1) * Mm + m1]);
        }

        // ---- L2 normalize ----
        float q0 = hn0 * hn0;
        float q1 = hn1 * hn1;
#pragma unroll
        for (int o = 16; o > 0; o >>= 1) {
            q0 += __shfl_down_sync(0xffffffffu, q0, o);
            q1 += __shfl_down_sync(0xffffffffu, q1, o);
        }
        if (lane == 0) redB[wid] = make_float2(q0, q1);
        __syncthreads();

        float n0 = redB[0].x + redB[1].x + redB[2].x + redB[3].x;
        float n1 = redB[0].y + redB[1].y + redB[2].y + redB[3].y;
        float r0 = 1.f / sqrtf(n0);
        float r1 = 1.f / sqrtf(n1);
        hold0 = hn0 * r0;
        hold1 = hn1 * r1;
        if (e < Dd) { h0[e] = hold0; h1[e] = hold1; }
        __syncthreads();   // h updated before next matvec
    }

    if (e < Dd) {
        out[((size_t)b * Mm + m0) * Dd + e] = hold0;
        out[((size_t)b * Mm + m1) * Dd + e] = hold1;
    }
}

// ================= launcher =================
extern "C" void kernel_launch(void* const* d_in, const int* in_sizes, int n_in,
                              void* d_out, int out_size) {
    const float* batch = (const float*)d_in[0];  // [B,S,L,D]
    const float* mult  = (const float*)d_in[1];  // [L,D]
    const float* keys  = (const float*)d_in[2];  // [M,D]
    const float* U     = (const float*)d_in[3];  // [D,D]
    const float* V     = (const float*)d_in[4];  // [D,D]
    const float* W     = (const float*)d_in[5];  // [D,D]
    const float* pa    = (const float*)d_in[6];  // scalar
    float* out = (float*)d_out;                  // [B,M,D]

    k_encode<<<Bb * Ss, 128>>>(batch, mult);
    k_project<<<(Bb * Ss) / R2, 128>>>(W, keys);
    k_scan<<<dim3(Mm / 2, Bb), 128>>>(keys, U, V, pa, out);
}